// round 16
// baseline (speedup 1.0000x reference)
#include <cuda_runtime.h>
#include <cuda_bf16.h>
#include <cstdint>

#define S_LEN 12
#define D_EMB 10
#define H1 50
#define H2 10
#define SPT 5      // samples per thread
#define TPB 256    // threads per block
#define NSM 148
#define BLKS_PER_SM 3

// ---------------------------------------------------------------------------
// Folded parameters.  Computed once per launch into g_fold (setup kernel),
// then copied into __constant__ c_sp (D2D memcpy node, graph-capturable).
//   scores[s]  = alpha*x_s + beta,  alpha = t*p_ww + p_wb, beta = t*p_bw + p_bb
//   W1 @ [emb_t; ctx] = t*u + xbar*v + c          (50-vectors)
//   h2[i] = relu(b2[i] + sum_j W2[i][j]*h1[j])    (W2 stored as i-pairs -> f32x2)
//   tm    = b3 + sum_i W3[i]*h2[i]
// ---------------------------------------------------------------------------
struct __align__(16) JRow {          // one 64B record per hidden unit j
    float4 uvc;                      // (u_j, v_j, c_j, 0)
    float2 w2[5];                    // (W2[2k][j], W2[2k+1][j]) k=0..4
    float2 pad;                      // -> 64B
};

struct __align__(16) SParams {
    JRow   rows[H1];                 // 3200 B
    float2 b2p[H2 / 2];
    float2 w3p[H2 / 2];
    float  p_ww, p_wb, p_bw, p_bb;
    float  b3;
    float  pad[3];
};

__device__   SParams g_fold;         // staging (written by setup kernel)
__constant__ SParams c_sp;           // read by main kernel via constant port

// ---------------------------------------------------------------------------
// Packed f32x2 helpers (Blackwell; ptxas never auto-fuses these from C++)
// ---------------------------------------------------------------------------
__device__ __forceinline__ unsigned long long pack2(float lo, float hi) {
    unsigned long long p;
    asm("mov.b64 %0, {%1, %2};" : "=l"(p) : "f"(lo), "f"(hi));
    return p;
}
__device__ __forceinline__ void unpack2(unsigned long long p, float& lo, float& hi) {
    asm("mov.b64 {%0, %1}, %2;" : "=f"(lo), "=f"(hi) : "l"(p));
}
__device__ __forceinline__ unsigned long long fma2(unsigned long long a,
                                                   unsigned long long b,
                                                   unsigned long long c) {
    unsigned long long d;
    asm("fma.rn.f32x2 %0, %1, %2, %3;" : "=l"(d) : "l"(a), "l"(b), "l"(c));
    return d;
}
__device__ __forceinline__ float rcp_fast(float x) {
    float y;
    asm("rcp.approx.f32 %0, %1;" : "=f"(y) : "f"(x));
    return y;
}

// ===========================================================================
// Setup kernel: fold raw weights into g_fold.  One block, 64 threads.
// ===========================================================================
__global__ void setup_kernel(const float* __restrict__ We_w, const float* __restrict__ We_b,
                             const float* __restrict__ Wt_w, const float* __restrict__ Wt_b,
                             const float* __restrict__ W1_w, const float* __restrict__ W1_b,
                             const float* __restrict__ W2_w, const float* __restrict__ W2_b,
                             const float* __restrict__ W3_w, const float* __restrict__ W3_b) {
    int j = threadIdx.x;
    if (j == 0) {
        float pww = 0.f, pwb = 0.f, pbw = 0.f, pbb = 0.f;
        for (int d = 0; d < D_EMB; d++) {
            pww = fmaf(We_w[d], Wt_w[d], pww);
            pwb = fmaf(We_w[d], Wt_b[d], pwb);
            pbw = fmaf(We_b[d], Wt_w[d], pbw);
            pbb = fmaf(We_b[d], Wt_b[d], pbb);
        }
        g_fold.p_ww = pww; g_fold.p_wb = pwb;
        g_fold.p_bw = pbw; g_fold.p_bb = pbb;
        g_fold.b3   = W3_b[0];
        g_fold.pad[0] = g_fold.pad[1] = g_fold.pad[2] = 0.f;
    }
    if (j < H1) {
        float u = 0.f, v = 0.f, c = W1_b[j];
        for (int d = 0; d < D_EMB; d++) {
            float w_t = W1_w[j * (2 * D_EMB) + d];          // emb_t half
            float w_c = W1_w[j * (2 * D_EMB) + D_EMB + d];  // ctx half
            u = fmaf(w_t, Wt_w[d], u);
            c = fmaf(w_t, Wt_b[d], c);
            v = fmaf(w_c, We_w[d], v);
            c = fmaf(w_c, We_b[d], c);
        }
        g_fold.rows[j].uvc = make_float4(u, v, c, 0.f);
        for (int k = 0; k < H2 / 2; k++)
            g_fold.rows[j].w2[k] =
                make_float2(W2_w[(2 * k) * H1 + j], W2_w[(2 * k + 1) * H1 + j]);
        g_fold.rows[j].pad = make_float2(0.f, 0.f);
    }
    if (j < H2 / 2) {
        g_fold.b2p[j] = make_float2(W2_b[2 * j], W2_b[2 * j + 1]);
        g_fold.w3p[j] = make_float2(W3_w[2 * j], W3_w[2 * j + 1]);
    }
}

// ---------------------------------------------------------------------------
// Phase-B pass over P samples: acc peak = P*5 u64 regs.  Weights from c_sp.
// ---------------------------------------------------------------------------
template <int P>
__device__ __forceinline__ void mlp_pass(const float* tt, const float* xb, float* tm) {
    unsigned long long acc[P][H2 / 2];
#pragma unroll
    for (int k = 0; k < P; k++)
#pragma unroll
        for (int q = 0; q < H2 / 2; q++)
            acc[k][q] = *reinterpret_cast<const unsigned long long*>(&c_sp.b2p[q]);

#pragma unroll 10
    for (int j = 0; j < H1; j++) {
        float4 uvc = c_sp.rows[j].uvc;
        ulonglong2 p01 = *reinterpret_cast<const ulonglong2*>(&c_sp.rows[j].w2[0]);
        ulonglong2 p23 = *reinterpret_cast<const ulonglong2*>(&c_sp.rows[j].w2[2]);
        ulonglong2 p4x = *reinterpret_cast<const ulonglong2*>(&c_sp.rows[j].w2[4]);
#pragma unroll
        for (int k = 0; k < P; k++) {
            float h = fmaxf(fmaf(tt[k], uvc.x, fmaf(xb[k], uvc.y, uvc.z)), 0.0f);
            unsigned long long hh = pack2(h, h);
            acc[k][0] = fma2(hh, p01.x, acc[k][0]);
            acc[k][1] = fma2(hh, p01.y, acc[k][1]);
            acc[k][2] = fma2(hh, p23.x, acc[k][2]);
            acc[k][3] = fma2(hh, p23.y, acc[k][3]);
            acc[k][4] = fma2(hh, p4x.x, acc[k][4]);
        }
    }
#pragma unroll
    for (int k = 0; k < P; k++) {
        float t = c_sp.b3;
#pragma unroll
        for (int q = 0; q < H2 / 2; q++) {
            float ax, ay;
            unpack2(acc[k][q], ax, ay);
            float2 w = c_sp.w3p[q];
            t = fmaf(w.x, fmaxf(ax, 0.f), t);
            t = fmaf(w.y, fmaxf(ay, 0.f), t);
        }
        tm[k] = t;
    }
}

// flags: bit0 = write tm, bit1 = write mask
__global__ void __launch_bounds__(TPB, BLKS_PER_SM)
mask_model_kernel(const float* __restrict__ inputs, const float* __restrict__ targets,
                  float* __restrict__ out, int B, int tm_off, int mask_off, int flags) {
    const int tid = blockIdx.x * blockDim.x + threadIdx.x;
    const int G   = gridDim.x * blockDim.x;
    const float LOG2E = 1.4426950408889634f;

    float tt[SPT], xb[SPT];

    // ---------------- Phase A: per-sample scores / softmax / mask ----------
#pragma unroll
    for (int k = 0; k < SPT; k++) {
        int b = tid + k * G;
        if (b >= B) { tt[k] = 0.f; xb[k] = 0.f; continue; }

        float x[S_LEN];
        {
            const float4* xp = reinterpret_cast<const float4*>(inputs + (size_t)b * S_LEN);
            float4 a0 = xp[0], a1 = xp[1], a2 = xp[2];
            x[0] = a0.x; x[1] = a0.y; x[2]  = a0.z; x[3]  = a0.w;
            x[4] = a1.x; x[5] = a1.y; x[6]  = a1.z; x[7]  = a1.w;
            x[8] = a2.x; x[9] = a2.y; x[10] = a2.z; x[11] = a2.w;
        }
        float t = targets[b];

        float alpha = fmaf(t, c_sp.p_ww, c_sp.p_wb);
        float beta  = fmaf(t, c_sp.p_bw, c_sp.p_bb);

        // scores are monotone in x: row max/min from xmax/xmin
        float xmx = x[0], xmn = x[0];
#pragma unroll
        for (int i = 1; i < S_LEN; i++) { xmx = fmaxf(xmx, x[i]); xmn = fminf(xmn, x[i]); }
        float xhi = (alpha >= 0.f) ? xmx : xmn;       // arg of score max
        float xlo = (alpha >= 0.f) ? xmn : xmx;       // arg of score min
        float smax = fmaf(alpha, xhi, beta);
        float r = rcp_fast(smax);
        float m2 = (smax > 0.f) ? 1.0f : fmaf(alpha, xlo, beta) * r;

        // e_i = exp2(((alpha*x_i+beta)*r - m2) * log2e) = exp2(A*x_i + C)
        float A = alpha * r * LOG2E;
        float C = fmaf(beta, r, -m2) * LOG2E;
        float e[S_LEN];
        float sum = 0.f, xbar = 0.f;
#pragma unroll
        for (int i = 0; i < S_LEN; i++) {
            e[i] = exp2f(fmaf(A, x[i], C));
            sum += e[i];
            xbar = fmaf(e[i], x[i], xbar);
        }
        float rs = rcp_fast(sum);
        tt[k] = t;
        xb[k] = xbar * rs;

        if (flags & 2) {
            // attn_i > mean(attn); rows sum to 1 => global mean == 1/S
            float thr = sum * (1.0f / (float)S_LEN);
            float4* op = reinterpret_cast<float4*>(out + mask_off + (size_t)b * S_LEN);
            op[0] = make_float4(e[0] > thr ? 1.f : 0.f, e[1] > thr ? 1.f : 0.f,
                                e[2] > thr ? 1.f : 0.f, e[3] > thr ? 1.f : 0.f);
            op[1] = make_float4(e[4] > thr ? 1.f : 0.f, e[5] > thr ? 1.f : 0.f,
                                e[6] > thr ? 1.f : 0.f, e[7] > thr ? 1.f : 0.f);
            op[2] = make_float4(e[8] > thr ? 1.f : 0.f, e[9] > thr ? 1.f : 0.f,
                                e[10] > thr ? 1.f : 0.f, e[11] > thr ? 1.f : 0.f);
        }
    }

    // ---------------- Phase B: two passes (3 + 2 samples) keeps acc regs low
    float tm[SPT];
    mlp_pass<3>(tt, xb, tm);
    mlp_pass<2>(tt + 3, xb + 3, tm + 3);

    if (flags & 1) {
#pragma unroll
        for (int k = 0; k < SPT; k++) {
            int b = tid + k * G;
            if (b < B) out[tm_off + b] = tm[k];
        }
    }
}

extern "C" void kernel_launch(void* const* d_in, const int* in_sizes, int n_in,
                              void* d_out, int out_size) {
    const float* inputs = (const float*)d_in[0];   // [B, S, 1]
    const float* targets = (const float*)d_in[1];  // [B, 1]
    const float* We_w = (const float*)d_in[2];
    const float* We_b = (const float*)d_in[3];
    const float* Wt_w = (const float*)d_in[4];
    const float* Wt_b = (const float*)d_in[5];
    const float* W1_w = (const float*)d_in[6];
    const float* W1_b = (const float*)d_in[7];
    const float* W2_w = (const float*)d_in[8];
    const float* W2_b = (const float*)d_in[9];
    const float* W3_w = (const float*)d_in[10];
    const float* W3_b = (const float*)d_in[11];

    int B = in_sizes[1];  // targets is [B,1]

    int tm_off = 0, mask_off = 0, flags = 3;
    if (out_size == B) {
        flags = 1;                       // tm only
    } else if (out_size == B * S_LEN) {
        flags = 2; mask_off = 0;         // mask only
    } else {
        flags = 3; tm_off = 0; mask_off = B;  // concat [tm, mask]
    }

    // 1) fold params on-device
    setup_kernel<<<1, 64>>>(We_w, We_b, Wt_w, Wt_b, W1_w, W1_b,
                            W2_w, W2_b, W3_w, W3_b);

    // 2) stage folded params into __constant__ (D2D async copy: capturable,
    //    allocation-free; both endpoints are static symbols)
    void* src = nullptr;
    cudaGetSymbolAddress(&src, g_fold);
    cudaMemcpyToSymbolAsync(c_sp, src, sizeof(SParams), 0,
                            cudaMemcpyDeviceToDevice, 0);

    // 3) main kernel — single balanced wave (grid multiple of SM count)
    int blocks = NSM * BLKS_PER_SM;                       // 444
    int need   = (B + TPB * SPT - 1) / (TPB * SPT);
    if (need > blocks) blocks = need;                     // safety for larger B

    mask_model_kernel<<<blocks, TPB>>>(inputs, targets,
                                       (float*)d_out, B, tm_off, mask_off, flags);
}

// round 17
// speedup vs baseline: 1.0502x; 1.0502x over previous
#include <cuda_runtime.h>
#include <cuda_bf16.h>
#include <cstdint>

#define S_LEN 12
#define D_EMB 10
#define H1 50
#define H2 10
#define SPT 5      // samples per thread
#define TPB 256    // threads per block
#define NSM 148
#define BLKS_PER_SM 3

// ---------------------------------------------------------------------------
// Folded parameters.  setup_kernel writes them DIRECTLY into the backing
// store of __constant__ c_sp (address obtained host-side via
// cudaGetSymbolAddress).  Coherence across the launch boundary is the same
// mechanism cudaMemcpyToSymbol relies on: constant caches are invalidated at
// kernel launch, and the STG lands in L2 before the next kernel's LDC.
//   scores[s]  = alpha*x_s + beta,  alpha = t*p_ww + p_wb, beta = t*p_bw + p_bb
//   W1 @ [emb_t; ctx] = t*u + xbar*v + c          (50-vectors)
//   h2[i] = relu(b2[i] + sum_j W2[i][j]*h1[j])    (W2 stored as i-pairs -> f32x2)
//   tm    = b3 + sum_i W3[i]*h2[i]
// ---------------------------------------------------------------------------
struct __align__(16) JRow {          // one 64B record per hidden unit j
    float4 uvc;                      // (u_j, v_j, c_j, 0)
    float2 w2[5];                    // (W2[2k][j], W2[2k+1][j]) k=0..4
    float2 pad;                      // -> 64B
};

struct __align__(16) SParams {
    JRow   rows[H1];                 // 3200 B
    float2 b2p[H2 / 2];
    float2 w3p[H2 / 2];
    float  p_ww, p_wb, p_bw, p_bb;
    float  b3;
    float  pad[3];
};

__constant__ SParams c_sp;           // read by main kernel via constant port

// ---------------------------------------------------------------------------
// Packed f32x2 helpers (Blackwell; ptxas never auto-fuses these from C++)
// ---------------------------------------------------------------------------
__device__ __forceinline__ unsigned long long pack2(float lo, float hi) {
    unsigned long long p;
    asm("mov.b64 %0, {%1, %2};" : "=l"(p) : "f"(lo), "f"(hi));
    return p;
}
__device__ __forceinline__ void unpack2(unsigned long long p, float& lo, float& hi) {
    asm("mov.b64 {%0, %1}, %2;" : "=f"(lo), "=f"(hi) : "l"(p));
}
__device__ __forceinline__ unsigned long long fma2(unsigned long long a,
                                                   unsigned long long b,
                                                   unsigned long long c) {
    unsigned long long d;
    asm("fma.rn.f32x2 %0, %1, %2, %3;" : "=l"(d) : "l"(a), "l"(b), "l"(c));
    return d;
}
__device__ __forceinline__ float rcp_fast(float x) {
    float y;
    asm("rcp.approx.f32 %0, %1;" : "=f"(y) : "f"(x));
    return y;
}

// ===========================================================================
// Setup kernel: fold raw weights and write straight into c_sp's backing.
// One block, 64 threads.  dst == &c_sp (device address of the symbol).
// ===========================================================================
__global__ void setup_kernel(SParams* __restrict__ dst,
                             const float* __restrict__ We_w, const float* __restrict__ We_b,
                             const float* __restrict__ Wt_w, const float* __restrict__ Wt_b,
                             const float* __restrict__ W1_w, const float* __restrict__ W1_b,
                             const float* __restrict__ W2_w, const float* __restrict__ W2_b,
                             const float* __restrict__ W3_w, const float* __restrict__ W3_b) {
    int j = threadIdx.x;
    if (j == 0) {
        float pww = 0.f, pwb = 0.f, pbw = 0.f, pbb = 0.f;
        for (int d = 0; d < D_EMB; d++) {
            pww = fmaf(We_w[d], Wt_w[d], pww);
            pwb = fmaf(We_w[d], Wt_b[d], pwb);
            pbw = fmaf(We_b[d], Wt_w[d], pbw);
            pbb = fmaf(We_b[d], Wt_b[d], pbb);
        }
        dst->p_ww = pww; dst->p_wb = pwb;
        dst->p_bw = pbw; dst->p_bb = pbb;
        dst->b3   = W3_b[0];
        dst->pad[0] = dst->pad[1] = dst->pad[2] = 0.f;
    }
    if (j < H1) {
        float u = 0.f, v = 0.f, c = W1_b[j];
        for (int d = 0; d < D_EMB; d++) {
            float w_t = W1_w[j * (2 * D_EMB) + d];          // emb_t half
            float w_c = W1_w[j * (2 * D_EMB) + D_EMB + d];  // ctx half
            u = fmaf(w_t, Wt_w[d], u);
            c = fmaf(w_t, Wt_b[d], c);
            v = fmaf(w_c, We_w[d], v);
            c = fmaf(w_c, We_b[d], c);
        }
        dst->rows[j].uvc = make_float4(u, v, c, 0.f);
        for (int k = 0; k < H2 / 2; k++)
            dst->rows[j].w2[k] =
                make_float2(W2_w[(2 * k) * H1 + j], W2_w[(2 * k + 1) * H1 + j]);
        dst->rows[j].pad = make_float2(0.f, 0.f);
    }
    if (j < H2 / 2) {
        dst->b2p[j] = make_float2(W2_b[2 * j], W2_b[2 * j + 1]);
        dst->w3p[j] = make_float2(W3_w[2 * j], W3_w[2 * j + 1]);
    }
}

// ---------------------------------------------------------------------------
// Phase-B pass over P samples: acc peak = P*5 u64 regs.  Weights from c_sp.
// ---------------------------------------------------------------------------
template <int P>
__device__ __forceinline__ void mlp_pass(const float* tt, const float* xb, float* tm) {
    unsigned long long acc[P][H2 / 2];
#pragma unroll
    for (int k = 0; k < P; k++)
#pragma unroll
        for (int q = 0; q < H2 / 2; q++)
            acc[k][q] = *reinterpret_cast<const unsigned long long*>(&c_sp.b2p[q]);

#pragma unroll 10
    for (int j = 0; j < H1; j++) {
        float4 uvc = c_sp.rows[j].uvc;
        ulonglong2 p01 = *reinterpret_cast<const ulonglong2*>(&c_sp.rows[j].w2[0]);
        ulonglong2 p23 = *reinterpret_cast<const ulonglong2*>(&c_sp.rows[j].w2[2]);
        ulonglong2 p4x = *reinterpret_cast<const ulonglong2*>(&c_sp.rows[j].w2[4]);
#pragma unroll
        for (int k = 0; k < P; k++) {
            float h = fmaxf(fmaf(tt[k], uvc.x, fmaf(xb[k], uvc.y, uvc.z)), 0.0f);
            unsigned long long hh = pack2(h, h);
            acc[k][0] = fma2(hh, p01.x, acc[k][0]);
            acc[k][1] = fma2(hh, p01.y, acc[k][1]);
            acc[k][2] = fma2(hh, p23.x, acc[k][2]);
            acc[k][3] = fma2(hh, p23.y, acc[k][3]);
            acc[k][4] = fma2(hh, p4x.x, acc[k][4]);
        }
    }
#pragma unroll
    for (int k = 0; k < P; k++) {
        float t = c_sp.b3;
#pragma unroll
        for (int q = 0; q < H2 / 2; q++) {
            float ax, ay;
            unpack2(acc[k][q], ax, ay);
            float2 w = c_sp.w3p[q];
            t = fmaf(w.x, fmaxf(ax, 0.f), t);
            t = fmaf(w.y, fmaxf(ay, 0.f), t);
        }
        tm[k] = t;
    }
}

// flags: bit0 = write tm, bit1 = write mask
__global__ void __launch_bounds__(TPB, BLKS_PER_SM)
mask_model_kernel(const float* __restrict__ inputs, const float* __restrict__ targets,
                  float* __restrict__ out, int B, int tm_off, int mask_off, int flags) {
    const int tid = blockIdx.x * blockDim.x + threadIdx.x;
    const int G   = gridDim.x * blockDim.x;
    const float LOG2E = 1.4426950408889634f;

    float tt[SPT], xb[SPT];

    // ---------------- Phase A: per-sample scores / softmax / mask ----------
#pragma unroll
    for (int k = 0; k < SPT; k++) {
        int b = tid + k * G;
        if (b >= B) { tt[k] = 0.f; xb[k] = 0.f; continue; }

        float x[S_LEN];
        {
            const float4* xp = reinterpret_cast<const float4*>(inputs + (size_t)b * S_LEN);
            float4 a0 = xp[0], a1 = xp[1], a2 = xp[2];
            x[0] = a0.x; x[1] = a0.y; x[2]  = a0.z; x[3]  = a0.w;
            x[4] = a1.x; x[5] = a1.y; x[6]  = a1.z; x[7]  = a1.w;
            x[8] = a2.x; x[9] = a2.y; x[10] = a2.z; x[11] = a2.w;
        }
        float t = targets[b];

        float alpha = fmaf(t, c_sp.p_ww, c_sp.p_wb);
        float beta  = fmaf(t, c_sp.p_bw, c_sp.p_bb);

        // scores are monotone in x: row max/min from xmax/xmin
        float xmx = x[0], xmn = x[0];
#pragma unroll
        for (int i = 1; i < S_LEN; i++) { xmx = fmaxf(xmx, x[i]); xmn = fminf(xmn, x[i]); }
        float xhi = (alpha >= 0.f) ? xmx : xmn;       // arg of score max
        float xlo = (alpha >= 0.f) ? xmn : xmx;       // arg of score min
        float smax = fmaf(alpha, xhi, beta);
        float r = rcp_fast(smax);
        float m2 = (smax > 0.f) ? 1.0f : fmaf(alpha, xlo, beta) * r;

        // e_i = exp2(((alpha*x_i+beta)*r - m2) * log2e) = exp2(A*x_i + C)
        float A = alpha * r * LOG2E;
        float C = fmaf(beta, r, -m2) * LOG2E;
        float e[S_LEN];
        float sum = 0.f, xbar = 0.f;
#pragma unroll
        for (int i = 0; i < S_LEN; i++) {
            e[i] = exp2f(fmaf(A, x[i], C));
            sum += e[i];
            xbar = fmaf(e[i], x[i], xbar);
        }
        float rs = rcp_fast(sum);
        tt[k] = t;
        xb[k] = xbar * rs;

        if (flags & 2) {
            // attn_i > mean(attn); rows sum to 1 => global mean == 1/S
            float thr = sum * (1.0f / (float)S_LEN);
            float4* op = reinterpret_cast<float4*>(out + mask_off + (size_t)b * S_LEN);
            op[0] = make_float4(e[0] > thr ? 1.f : 0.f, e[1] > thr ? 1.f : 0.f,
                                e[2] > thr ? 1.f : 0.f, e[3] > thr ? 1.f : 0.f);
            op[1] = make_float4(e[4] > thr ? 1.f : 0.f, e[5] > thr ? 1.f : 0.f,
                                e[6] > thr ? 1.f : 0.f, e[7] > thr ? 1.f : 0.f);
            op[2] = make_float4(e[8] > thr ? 1.f : 0.f, e[9] > thr ? 1.f : 0.f,
                                e[10] > thr ? 1.f : 0.f, e[11] > thr ? 1.f : 0.f);
        }
    }

    // ---------------- Phase B: two passes (3 + 2 samples) keeps acc regs low
    float tm[SPT];
    mlp_pass<3>(tt, xb, tm);
    mlp_pass<2>(tt + 3, xb + 3, tm + 3);

    if (flags & 1) {
#pragma unroll
        for (int k = 0; k < SPT; k++) {
            int b = tid + k * G;
            if (b < B) out[tm_off + b] = tm[k];
        }
    }
}

extern "C" void kernel_launch(void* const* d_in, const int* in_sizes, int n_in,
                              void* d_out, int out_size) {
    const float* inputs = (const float*)d_in[0];   // [B, S, 1]
    const float* targets = (const float*)d_in[1];  // [B, 1]
    const float* We_w = (const float*)d_in[2];
    const float* We_b = (const float*)d_in[3];
    const float* Wt_w = (const float*)d_in[4];
    const float* Wt_b = (const float*)d_in[5];
    const float* W1_w = (const float*)d_in[6];
    const float* W1_b = (const float*)d_in[7];
    const float* W2_w = (const float*)d_in[8];
    const float* W2_b = (const float*)d_in[9];
    const float* W3_w = (const float*)d_in[10];
    const float* W3_b = (const float*)d_in[11];

    int B = in_sizes[1];  // targets is [B,1]

    int tm_off = 0, mask_off = 0, flags = 3;
    if (out_size == B) {
        flags = 1;                       // tm only
    } else if (out_size == B * S_LEN) {
        flags = 2; mask_off = 0;         // mask only
    } else {
        flags = 3; tm_off = 0; mask_off = B;  // concat [tm, mask]
    }

    // Fold params straight into c_sp's backing store (no memcpy node).
    // cudaGetSymbolAddress is a host-side query: capture-legal, alloc-free.
    void* c_addr = nullptr;
    cudaGetSymbolAddress(&c_addr, c_sp);
    setup_kernel<<<1, 64>>>((SParams*)c_addr,
                            We_w, We_b, Wt_w, Wt_b, W1_w, W1_b,
                            W2_w, W2_b, W3_w, W3_b);

    // Main kernel — single balanced wave (grid multiple of SM count)
    int blocks = NSM * BLKS_PER_SM;                       // 444
    int need   = (B + TPB * SPT - 1) / (TPB * SPT);
    if (need > blocks) blocks = need;                     // safety for larger B

    mask_model_kernel<<<blocks, TPB>>>(inputs, targets,
                                       (float*)d_out, B, tm_off, mask_off, flags);
}